// round 3
// baseline (speedup 1.0000x reference)
#include <cuda_runtime.h>
#include <math.h>

#define Bsz   4096
#define Lh    64
#define Dh    16
#define Hh    128
#define ROWS  32
#define THREADS 512
#define CTAS  128
#define HEAD_IN 144
#define OUTD  60

// packed f32x2 FMA: only reachable via PTX (ptxas won't auto-fuse)
#define FMA2(acc, a, b) \
    asm("fma.rn.f32x2 %0, %1, %2, %3;" : "=l"(acc) : "l"(a), "l"(b), "l"(acc))
#define PACK2(d, lo, hi) \
    asm("mov.b64 %0, {%1, %2};" : "=l"(d) : "f"(lo), "f"(hi))

__device__ __forceinline__ float2 unpack2(unsigned long long v) {
    float2 r;
    asm("mov.b64 {%0, %1}, %2;" : "=f"(r.x), "=f"(r.y) : "l"(v));
    return r;
}

struct SM {
    float h[2][ROWS][Hh];    // hidden state per layer
    float c[2][ROWS][Hh];    // cell state per layer
    float xin[ROWS][Hh];     // projected input x_t
    float ht[ROWS][Hh];      // h_tilde scratch
    float sv[ROWS][Hh];      // saved encoded state at t=last
    float wp[Dh][Hh];        // Wp cached
    float histb[ROWS][Dh];   // history row slice at t
    float msk[ROWS];
    float dec[ROWS];
    int   last[ROWS];
};

__device__ __forceinline__ float sigf(float x) {
    return 1.0f / (1.0f + expf(-x));
}

__device__ __forceinline__ float fixv(float x) {
    if (!(x == x)) return 0.0f;
    if (x > 1e38f) return 1e4f;
    if (x < -1e38f) return -1e4f;
    return x;
}

__global__ void __launch_bounds__(THREADS, 1)
tlstm_kernel(const float* __restrict__ history, const float* __restrict__ hmask,
             const float* __restrict__ Wp,  const float* __restrict__ bp,
             const float* __restrict__ Wx,  const float* __restrict__ bx,
             const float* __restrict__ Uh,  const float* __restrict__ Wd,
             const float* __restrict__ bd,  const float* __restrict__ Wt,
             const float* __restrict__ bt,  const float* __restrict__ ln_g,
             const float* __restrict__ ln_b, const float* __restrict__ W1,
             const float* __restrict__ b1,  const float* __restrict__ W2,
             const float* __restrict__ b2,  float* __restrict__ out)
{
    extern __shared__ char smraw[];
    SM* sm = reinterpret_cast<SM*>(smraw);

    const int tid  = threadIdx.x;
    const int b0   = blockIdx.x * ROWS;
    const int w    = tid >> 5;
    const int lane = tid & 31;
    const int wk   = w & 7;
    const int wr   = w >> 3;
    const int half = lane >> 4;
    const int kk   = lane & 15;
    const int k    = wk * 16 + kk;          // output channel
    const int rb   = wr * 16 + half * 8;    // first of 8 rows

    for (int i = tid; i < 2 * ROWS * Hh; i += THREADS) {
        (&sm->h[0][0][0])[i] = 0.0f;
        (&sm->c[0][0][0])[i] = 0.0f;
    }
    for (int i = tid; i < Dh * Hh; i += THREADS)
        (&sm->wp[0][0])[i] = Wp[i];
    if (tid < ROWS) {
        const float* mp = hmask + (size_t)(b0 + tid) * Lh;
        float s = 0.0f;
        for (int t = 0; t < Lh; t++) s += mp[t];
        s = fminf(fmaxf(s, 1.0f), (float)Lh);
        sm->last[tid] = (int)s - 1;
    }
    __syncthreads();

    const float bpk  = bp[k];
    const float bxi0 = bx[(0*4+1)*Hh + k], bxo0 = bx[(0*4+2)*Hh + k], bxc0 = bx[(0*4+3)*Hh + k];
    const float bxi1 = bx[(1*4+1)*Hh + k], bxo1 = bx[(1*4+2)*Hh + k], bxc1 = bx[(1*4+3)*Hh + k];
    const float bd0  = bd[k],      bd1 = bd[Hh + k];
    const float wt0  = Wt[k],      wt1 = Wt[Hh + k];
    const float bt0  = bt[k],      bt1 = bt[Hh + k];

    // ================= time loop =================
    for (int t = 0; t < Lh; t++) {
        {
            int r = tid >> 4, d = tid & 15;
            sm->histb[r][d] = history[((size_t)(b0 + r) * Lh + t) * Dh + d];
            if (tid < ROWS)
                sm->msk[tid] = hmask[(size_t)(b0 + tid) * Lh + t];
        }
        __syncthreads();

        if (tid < ROWS) {
            float dd = fmaxf(sm->histb[tid][5], 0.0f);
            sm->dec[tid] = 1.0f / logf(2.718281828459045f + dd);
        }
        // x_t = hist @ Wp + bp
        {
            float acc[8];
            #pragma unroll
            for (int rr = 0; rr < 8; rr++) acc[rr] = bpk;
            #pragma unroll
            for (int d = 0; d < Dh; d++) {
                float wv = sm->wp[d][k];
                #pragma unroll
                for (int rr = 0; rr < 8; rr++)
                    acc[rr] += sm->histb[rb + rr][d] * wv;
            }
            #pragma unroll
            for (int rr = 0; rr < 8; rr++) sm->xin[rb + rr][k] = acc[rr];
        }
        __syncthreads();

        #pragma unroll
        for (int l = 0; l < 2; l++) {
            const float* inp  = (l == 0) ? &sm->xin[0][0] : &sm->h[0][0][0];
            float*       hcur = &sm->h[l][0][0];
            const float* pWxi = Wx + ((size_t)(l*4+1) * Hh) * Hh + k;
            const float* pWxo = Wx + ((size_t)(l*4+2) * Hh) * Hh + k;
            const float* pWxc = Wx + ((size_t)(l*4+3) * Hh) * Hh + k;
            const float* pUhi = Uh + ((size_t)(l*4+1) * Hh) * Hh + k;
            const float* pUho = Uh + ((size_t)(l*4+2) * Hh) * Hh + k;
            const float* pUhc = Uh + ((size_t)(l*4+3) * Hh) * Hh + k;

            float it[8], ot[8];

            // ---- pass 1: i and o gates (packed over j-pairs) ----
            {
                unsigned long long zi2[8], zo2[8];
                const float bi = l ? bxi1 : bxi0;
                const float bo = l ? bxo1 : bxo0;
                #pragma unroll
                for (int rr = 0; rr < 8; rr++) {
                    PACK2(zi2[rr], bi, 0.0f);
                    PACK2(zo2[rr], bo, 0.0f);
                }
                for (int j = 0; j < Hh; j += 4) {
                    const int j0 = j*Hh, j1 = j0+Hh, j2 = j1+Hh, j3 = j2+Hh;
                    unsigned long long wi2[2], wo2[2], ui2[2], uo2[2];
                    PACK2(wi2[0], pWxi[j0], pWxi[j1]); PACK2(wi2[1], pWxi[j2], pWxi[j3]);
                    PACK2(wo2[0], pWxo[j0], pWxo[j1]); PACK2(wo2[1], pWxo[j2], pWxo[j3]);
                    PACK2(ui2[0], pUhi[j0], pUhi[j1]); PACK2(ui2[1], pUhi[j2], pUhi[j3]);
                    PACK2(uo2[0], pUho[j0], pUho[j1]); PACK2(uo2[1], pUho[j2], pUho[j3]);
                    #pragma unroll
                    for (int rr = 0; rr < 8; rr++) {
                        const int r = rb + rr;
                        ulonglong2 xu = *reinterpret_cast<const ulonglong2*>(inp  + r*Hh + j);
                        ulonglong2 hu = *reinterpret_cast<const ulonglong2*>(hcur + r*Hh + j);
                        FMA2(zi2[rr], xu.x, wi2[0]); FMA2(zi2[rr], xu.y, wi2[1]);
                        FMA2(zi2[rr], hu.x, ui2[0]); FMA2(zi2[rr], hu.y, ui2[1]);
                        FMA2(zo2[rr], xu.x, wo2[0]); FMA2(zo2[rr], xu.y, wo2[1]);
                        FMA2(zo2[rr], hu.x, uo2[0]); FMA2(zo2[rr], hu.y, uo2[1]);
                    }
                }
                #pragma unroll
                for (int rr = 0; rr < 8; rr++) {
                    float2 a = unpack2(zi2[rr]);
                    float2 b = unpack2(zo2[rr]);
                    it[rr] = sigf(a.x + a.y);
                    ot[rr] = sigf(b.x + b.y);
                }
            }

            // ---- pass 2: c gate (packed) ----
            float htl[8];
            {
                unsigned long long zc2[8];
                const float bc = l ? bxc1 : bxc0;
                #pragma unroll
                for (int rr = 0; rr < 8; rr++) PACK2(zc2[rr], bc, 0.0f);
                for (int j = 0; j < Hh; j += 4) {
                    const int j0 = j*Hh, j1 = j0+Hh, j2 = j1+Hh, j3 = j2+Hh;
                    unsigned long long wc2[2], uc2[2];
                    PACK2(wc2[0], pWxc[j0], pWxc[j1]); PACK2(wc2[1], pWxc[j2], pWxc[j3]);
                    PACK2(uc2[0], pUhc[j0], pUhc[j1]); PACK2(uc2[1], pUhc[j2], pUhc[j3]);
                    #pragma unroll
                    for (int rr = 0; rr < 8; rr++) {
                        const int r = rb + rr;
                        ulonglong2 xu = *reinterpret_cast<const ulonglong2*>(inp  + r*Hh + j);
                        ulonglong2 hu = *reinterpret_cast<const ulonglong2*>(hcur + r*Hh + j);
                        FMA2(zc2[rr], xu.x, wc2[0]); FMA2(zc2[rr], xu.y, wc2[1]);
                        FMA2(zc2[rr], hu.x, uc2[0]); FMA2(zc2[rr], hu.y, uc2[1]);
                    }
                }
                #pragma unroll
                for (int rr = 0; rr < 8; rr++) {
                    float2 a = unpack2(zc2[rr]);
                    htl[rr]  = tanhf(a.x + a.y) + it[rr];
                    sm->ht[rb + rr][k] = htl[rr];
                }
            }
            __syncthreads();

            // ---- h_short = tanh(h_tilde @ Wd + bd), packed ----
            const float* pWd = Wd + (size_t)l * Hh * Hh + k;
            const float  bdl = l ? bd1 : bd0;
            unsigned long long hs2[8];
            #pragma unroll
            for (int rr = 0; rr < 8; rr++) PACK2(hs2[rr], bdl, 0.0f);
            for (int j = 0; j < Hh; j += 4) {
                const int j0 = j*Hh, j1 = j0+Hh, j2 = j1+Hh, j3 = j2+Hh;
                unsigned long long wd2[2];
                PACK2(wd2[0], pWd[j0], pWd[j1]); PACK2(wd2[1], pWd[j2], pWd[j3]);
                #pragma unroll
                for (int rr = 0; rr < 8; rr++) {
                    ulonglong2 t4 = *reinterpret_cast<const ulonglong2*>(&sm->ht[rb + rr][j]);
                    FMA2(hs2[rr], t4.x, wd2[0]); FMA2(hs2[rr], t4.y, wd2[1]);
                }
            }

            const float wtl = l ? wt1 : wt0;
            const float btl = l ? bt1 : bt0;
            #pragma unroll
            for (int rr = 0; rr < 8; rr++) {
                const int r = rb + rr;
                float2 av   = unpack2(hs2[rr]);
                float hs    = tanhf(av.x + av.y);
                float dt    = sigf(sm->dec[r] * wtl + btl);
                float hstar = (htl[rr] - hs) + hs * dt;
                float cold  = sm->c[l][r][k];
                float cn    = tanhf(hstar + ot[rr] * cold);
                float hn    = ot[rr] * tanhf(cn);
                float m     = sm->msk[r];
                float hv    = m * hn + (1.0f - m) * hcur[r*Hh + k];
                float cv    = m * cn + (1.0f - m) * cold;
                sm->c[l][r][k] = cv;
                hcur[r*Hh + k] = hv;
                if (l == 1 && t == sm->last[r])
                    sm->sv[r][k] = m * hv;
            }
            __syncthreads();
        }
    }

    // ================= forecast head =================
    {
        int r = tid >> 4, d = tid & 15;
        sm->histb[r][d] = history[((size_t)(b0 + r) * Lh + sm->last[r]) * Dh + d];
    }
    __syncthreads();

    const unsigned FULL = 0xffffffffu;
    #pragma unroll
    for (int rr = 0; rr < 2; rr++) {
        const int r = w * 2 + rr;

        float s = 0.0f, s2 = 0.0f;
        for (int i = lane; i < HEAD_IN; i += 32) {
            float v = (i < 16) ? sm->histb[r][i] : sm->sv[r][i - 16];
            s += v; s2 += v * v;
        }
        #pragma unroll
        for (int off = 16; off; off >>= 1) {
            s  += __shfl_xor_sync(FULL, s,  off);
            s2 += __shfl_xor_sync(FULL, s2, off);
        }
        float mean = s / (float)HEAD_IN;
        float var  = s2 / (float)HEAD_IN - mean * mean;
        float rstd = rsqrtf(var + 1e-5f);

        const int j0 = lane * 4;
        float4 acc = *reinterpret_cast<const float4*>(b1 + j0);
        for (int i = 0; i < HEAD_IN; i++) {
            float v  = (i < 16) ? sm->histb[r][i] : sm->sv[r][i - 16];
            float sn = (v - mean) * rstd * ln_g[i] + ln_b[i];
            float4 w4 = *reinterpret_cast<const float4*>(W1 + i * Hh + j0);
            acc.x += sn * w4.x; acc.y += sn * w4.y;
            acc.z += sn * w4.z; acc.w += sn * w4.w;
        }
        float y[4] = { fmaxf(acc.x, 0.0f), fmaxf(acc.y, 0.0f),
                       fmaxf(acc.z, 0.0f), fmaxf(acc.w, 0.0f) };

        const int o0 = lane, o1 = lane + 32;
        float a0 = b2[o0];
        float a1 = (o1 < OUTD) ? b2[o1] : 0.0f;
        #pragma unroll
        for (int q = 0; q < 4; q++) {
            float yq = y[q];
            #pragma unroll 8
            for (int src = 0; src < 32; src++) {
                float v = __shfl_sync(FULL, yq, src);
                int   j = src * 4 + q;
                a0 += v * W2[j * OUTD + o0];
                if (o1 < OUTD) a1 += v * W2[j * OUTD + o1];
            }
        }
        size_t ob = (size_t)(b0 + r) * OUTD;
        out[ob + o0] = fixv(a0);
        if (o1 < OUTD) out[ob + o1] = fixv(a1);
    }
}

extern "C" void kernel_launch(void* const* d_in, const int* in_sizes, int n_in,
                              void* d_out, int out_size)
{
    const float* history = (const float*)d_in[0];
    const float* hmask   = (const float*)d_in[1];
    const float* Wp      = (const float*)d_in[2];
    const float* bp      = (const float*)d_in[3];
    const float* Wx      = (const float*)d_in[4];
    const float* bx      = (const float*)d_in[5];
    const float* Uh      = (const float*)d_in[6];
    const float* Wd      = (const float*)d_in[7];
    const float* bd      = (const float*)d_in[8];
    const float* Wt      = (const float*)d_in[9];
    const float* bt      = (const float*)d_in[10];
    const float* ln_g    = (const float*)d_in[11];
    const float* ln_b    = (const float*)d_in[12];
    const float* W1      = (const float*)d_in[13];
    const float* b1      = (const float*)d_in[14];
    const float* W2      = (const float*)d_in[15];
    const float* b2      = (const float*)d_in[16];

    cudaFuncSetAttribute(tlstm_kernel,
                         cudaFuncAttributeMaxDynamicSharedMemorySize,
                         (int)sizeof(SM));
    tlstm_kernel<<<CTAS, THREADS, sizeof(SM)>>>(
        history, hmask, Wp, bp, Wx, bx, Uh, Wd, bd, Wt, bt,
        ln_g, ln_b, W1, b1, W2, b2, (float*)d_out);
}

// round 4
// speedup vs baseline: 1.1006x; 1.1006x over previous
#include <cuda_runtime.h>
#include <math.h>

#define Bsz   4096
#define Lh    64
#define Dh    16
#define Hh    128
#define ROWS  32
#define THREADS 512
#define CTAS  128
#define HEAD_IN 144
#define OUTD  60
#define SQ    (Hh*Hh)   // 16384 floats per gate matrix

typedef unsigned long long ull;

// packed f32x2 FMA: only reachable via PTX (ptxas won't auto-fuse)
#define FMA2(acc, a, b) \
    asm("fma.rn.f32x2 %0, %1, %2, %3;" : "=l"(acc) : "l"(a), "l"(b), "l"(acc))
#define PACK2(d, lo, hi) \
    asm("mov.b64 %0, {%1, %2};" : "=l"(d) : "f"(lo), "f"(hi))

__device__ __forceinline__ float2 unpack2(ull v) {
    float2 r;
    asm("mov.b64 {%0, %1}, %2;" : "=f"(r.x), "=f"(r.y) : "l"(v));
    return r;
}

struct SM {
    float h[2][ROWS][Hh];
    float c[2][ROWS][Hh];
    float xin[ROWS][Hh];
    float ht[ROWS][Hh];
    float sv[ROWS][Hh];
    float wp[Dh][Hh];
    float histb[ROWS][Dh];
    float msk[ROWS];
    float dec[ROWS];
    int   last[ROWS];
};

__device__ __forceinline__ float sigf(float x) {
    return 1.0f / (1.0f + expf(-x));
}

__device__ __forceinline__ float fixv(float x) {
    if (!(x == x)) return 0.0f;
    if (x > 1e38f) return 1e4f;
    if (x < -1e38f) return -1e4f;
    return x;
}

__global__ void __launch_bounds__(THREADS, 1)
tlstm_kernel(const float* __restrict__ history, const float* __restrict__ hmask,
             const float* __restrict__ Wp,  const float* __restrict__ bp,
             const float* __restrict__ Wx,  const float* __restrict__ bx,
             const float* __restrict__ Uh,  const float* __restrict__ Wd,
             const float* __restrict__ bd,  const float* __restrict__ Wt,
             const float* __restrict__ bt,  const float* __restrict__ ln_g,
             const float* __restrict__ ln_b, const float* __restrict__ W1,
             const float* __restrict__ b1,  const float* __restrict__ W2,
             const float* __restrict__ b2,  float* __restrict__ out)
{
    extern __shared__ char smraw[];
    SM* sm = reinterpret_cast<SM*>(smraw);

    const int tid  = threadIdx.x;
    const int b0   = blockIdx.x * ROWS;
    const int w    = tid >> 5;
    const int lane = tid & 31;
    const int wk   = w & 7;
    const int wr   = w >> 3;
    const int half = lane >> 4;
    const int kk   = lane & 15;
    const int k    = wk * 16 + kk;          // output channel
    const int rb   = wr * 16 + half * 8;    // first of 8 rows

    for (int i = tid; i < 2 * ROWS * Hh; i += THREADS) {
        (&sm->h[0][0][0])[i] = 0.0f;
        (&sm->c[0][0][0])[i] = 0.0f;
    }
    for (int i = tid; i < Dh * Hh; i += THREADS)
        (&sm->wp[0][0])[i] = Wp[i];
    if (tid < ROWS) {
        const float* mp = hmask + (size_t)(b0 + tid) * Lh;
        float s = 0.0f;
        for (int t = 0; t < Lh; t++) s += mp[t];
        s = fminf(fmaxf(s, 1.0f), (float)Lh);
        sm->last[tid] = (int)s - 1;
    }
    __syncthreads();

    const float bpk  = bp[k];
    const float bxi0 = bx[1*Hh + k], bxo0 = bx[2*Hh + k], bxc0 = bx[3*Hh + k];
    const float bxi1 = bx[5*Hh + k], bxo1 = bx[6*Hh + k], bxc1 = bx[7*Hh + k];
    const float bd0  = bd[k],      bd1 = bd[Hh + k];
    const float wt0  = Wt[k],      wt1 = Wt[Hh + k];
    const float bt0  = bt[k],      bt1 = bt[Hh + k];

    // ================= time loop =================
    for (int t = 0; t < Lh; t++) {
        {
            int r = tid >> 4, d = tid & 15;
            sm->histb[r][d] = history[((size_t)(b0 + r) * Lh + t) * Dh + d];
            if (tid < ROWS)
                sm->msk[tid] = hmask[(size_t)(b0 + tid) * Lh + t];
        }
        __syncthreads();

        if (tid < ROWS) {
            float dd = fmaxf(sm->histb[tid][5], 0.0f);
            sm->dec[tid] = 1.0f / logf(2.718281828459045f + dd);
        }
        // x_t = hist @ Wp + bp
        {
            float acc[8];
            #pragma unroll
            for (int rr = 0; rr < 8; rr++) acc[rr] = bpk;
            #pragma unroll
            for (int d = 0; d < Dh; d++) {
                float wv = sm->wp[d][k];
                #pragma unroll
                for (int rr = 0; rr < 8; rr++)
                    acc[rr] += sm->histb[rb + rr][d] * wv;
            }
            #pragma unroll
            for (int rr = 0; rr < 8; rr++) sm->xin[rb + rr][k] = acc[rr];
        }
        __syncthreads();

        #pragma unroll
        for (int l = 0; l < 2; l++) {
            const float* inp  = (l == 0) ? &sm->xin[0][0] : &sm->h[0][0][0];
            float*       hcur = &sm->h[l][0][0];
            // single base pointer per matrix; gate streams reached via
            // compile-time immediate offsets (i at +SQ, o at +2SQ, c at +3SQ)
            const float* px = Wx + (size_t)l * 4 * SQ + SQ + k;
            const float* pu = Uh + (size_t)l * 4 * SQ + SQ + k;

            // packed accumulators: 3 gates x 8 rows (lo = even j, hi = odd j)
            ull zi2[8], zo2[8], zc2[8];
            {
                const float bi = l ? bxi1 : bxi0;
                const float bo = l ? bxo1 : bxo0;
                const float bc = l ? bxc1 : bxc0;
                #pragma unroll
                for (int rr = 0; rr < 8; rr++) {
                    PACK2(zi2[rr], bi, 0.0f);
                    PACK2(zo2[rr], bo, 0.0f);
                    PACK2(zc2[rr], bc, 0.0f);
                }
            }

            // single-pass gate GEMV, j-pairs packed into f32x2
            #pragma unroll 2
            for (int j = 0; j < Hh; j += 2) {
                ull wi2, wo2, wc2, ui2, uo2, uc2;
                PACK2(wi2, px[0],      px[Hh]);
                PACK2(wo2, px[SQ],     px[SQ + Hh]);
                PACK2(wc2, px[2*SQ],   px[2*SQ + Hh]);
                PACK2(ui2, pu[0],      pu[Hh]);
                PACK2(uo2, pu[SQ],     pu[SQ + Hh]);
                PACK2(uc2, pu[2*SQ],   pu[2*SQ + Hh]);
                #pragma unroll
                for (int rr = 0; rr < 8; rr++) {
                    const int r = rb + rr;
                    ull xu = *reinterpret_cast<const ull*>(inp  + r*Hh + j);
                    ull hu = *reinterpret_cast<const ull*>(hcur + r*Hh + j);
                    FMA2(zi2[rr], xu, wi2);
                    FMA2(zo2[rr], xu, wo2);
                    FMA2(zc2[rr], xu, wc2);
                    FMA2(zi2[rr], hu, ui2);
                    FMA2(zo2[rr], hu, uo2);
                    FMA2(zc2[rr], hu, uc2);
                }
                px += 2*Hh;
                pu += 2*Hh;
            }

            float it[8], ot[8], htl[8];
            #pragma unroll
            for (int rr = 0; rr < 8; rr++) {
                float2 a = unpack2(zi2[rr]);
                float2 b = unpack2(zo2[rr]);
                float2 c = unpack2(zc2[rr]);
                it[rr]  = sigf(a.x + a.y);
                ot[rr]  = sigf(b.x + b.y);
                htl[rr] = tanhf(c.x + c.y) + it[rr];
                sm->ht[rb + rr][k] = htl[rr];
            }
            __syncthreads();

            // h_short = tanh(h_tilde @ Wd + bd), packed
            const float* pd = Wd + (size_t)l * SQ + k;
            const float  bdl = l ? bd1 : bd0;
            ull hs2[8];
            #pragma unroll
            for (int rr = 0; rr < 8; rr++) PACK2(hs2[rr], bdl, 0.0f);
            #pragma unroll 4
            for (int j = 0; j < Hh; j += 2) {
                ull wd2;
                PACK2(wd2, pd[0], pd[Hh]);
                #pragma unroll
                for (int rr = 0; rr < 8; rr++) {
                    ull t2 = *reinterpret_cast<const ull*>(&sm->ht[rb + rr][j]);
                    FMA2(hs2[rr], t2, wd2);
                }
                pd += 2*Hh;
            }

            const float wtl = l ? wt1 : wt0;
            const float btl = l ? bt1 : bt0;
            #pragma unroll
            for (int rr = 0; rr < 8; rr++) {
                const int r = rb + rr;
                float2 av   = unpack2(hs2[rr]);
                float hs    = tanhf(av.x + av.y);
                float dt    = sigf(sm->dec[r] * wtl + btl);
                float hstar = (htl[rr] - hs) + hs * dt;
                float cold  = sm->c[l][r][k];
                float cn    = tanhf(hstar + ot[rr] * cold);
                float hn    = ot[rr] * tanhf(cn);
                float m     = sm->msk[r];
                float hv    = m * hn + (1.0f - m) * hcur[r*Hh + k];
                float cv    = m * cn + (1.0f - m) * cold;
                sm->c[l][r][k] = cv;
                hcur[r*Hh + k] = hv;
                if (l == 1 && t == sm->last[r])
                    sm->sv[r][k] = m * hv;
            }
            __syncthreads();
        }
    }

    // ================= forecast head =================
    {
        int r = tid >> 4, d = tid & 15;
        sm->histb[r][d] = history[((size_t)(b0 + r) * Lh + sm->last[r]) * Dh + d];
    }
    __syncthreads();

    const unsigned FULL = 0xffffffffu;
    #pragma unroll
    for (int rr = 0; rr < 2; rr++) {
        const int r = w * 2 + rr;

        float s = 0.0f, s2 = 0.0f;
        for (int i = lane; i < HEAD_IN; i += 32) {
            float v = (i < 16) ? sm->histb[r][i] : sm->sv[r][i - 16];
            s += v; s2 += v * v;
        }
        #pragma unroll
        for (int off = 16; off; off >>= 1) {
            s  += __shfl_xor_sync(FULL, s,  off);
            s2 += __shfl_xor_sync(FULL, s2, off);
        }
        float mean = s / (float)HEAD_IN;
        float var  = s2 / (float)HEAD_IN - mean * mean;
        float rstd = rsqrtf(var + 1e-5f);

        const int j0 = lane * 4;
        float4 acc = *reinterpret_cast<const float4*>(b1 + j0);
        for (int i = 0; i < HEAD_IN; i++) {
            float v  = (i < 16) ? sm->histb[r][i] : sm->sv[r][i - 16];
            float sn = (v - mean) * rstd * ln_g[i] + ln_b[i];
            float4 w4 = *reinterpret_cast<const float4*>(W1 + i * Hh + j0);
            acc.x += sn * w4.x; acc.y += sn * w4.y;
            acc.z += sn * w4.z; acc.w += sn * w4.w;
        }
        float y[4] = { fmaxf(acc.x, 0.0f), fmaxf(acc.y, 0.0f),
                       fmaxf(acc.z, 0.0f), fmaxf(acc.w, 0.0f) };

        const int o0 = lane, o1 = lane + 32;
        float a0 = b2[o0];
        float a1 = (o1 < OUTD) ? b2[o1] : 0.0f;
        #pragma unroll
        for (int q = 0; q < 4; q++) {
            float yq = y[q];
            #pragma unroll 8
            for (int src = 0; src < 32; src++) {
                float v = __shfl_sync(FULL, yq, src);
                int   j = src * 4 + q;
                a0 += v * W2[j * OUTD + o0];
                if (o1 < OUTD) a1 += v * W2[j * OUTD + o1];
            }
        }
        size_t ob = (size_t)(b0 + r) * OUTD;
        out[ob + o0] = fixv(a0);
        if (o1 < OUTD) out[ob + o1] = fixv(a1);
    }
}

extern "C" void kernel_launch(void* const* d_in, const int* in_sizes, int n_in,
                              void* d_out, int out_size)
{
    const float* history = (const float*)d_in[0];
    const float* hmask   = (const float*)d_in[1];
    const float* Wp      = (const float*)d_in[2];
    const float* bp      = (const float*)d_in[3];
    const float* Wx      = (const float*)d_in[4];
    const float* bx      = (const float*)d_in[5];
    const float* Uh      = (const float*)d_in[6];
    const float* Wd      = (const float*)d_in[7];
    const float* bd      = (const float*)d_in[8];
    const float* Wt      = (const float*)d_in[9];
    const float* bt      = (const float*)d_in[10];
    const float* ln_g    = (const float*)d_in[11];
    const float* ln_b    = (const float*)d_in[12];
    const float* W1      = (const float*)d_in[13];
    const float* b1      = (const float*)d_in[14];
    const float* W2      = (const float*)d_in[15];
    const float* b2      = (const float*)d_in[16];

    cudaFuncSetAttribute(tlstm_kernel,
                         cudaFuncAttributeMaxDynamicSharedMemorySize,
                         (int)sizeof(SM));
    tlstm_kernel<<<CTAS, THREADS, sizeof(SM)>>>(
        history, hmask, Wp, bp, Wx, bx, Uh, Wd, bd, Wt, bt,
        ln_g, ln_b, W1, b1, W2, b2, (float*)d_out);
}

// round 5
// speedup vs baseline: 1.1689x; 1.0620x over previous
#include <cuda_runtime.h>
#include <math.h>

#define Bsz   4096
#define Lh    64
#define Dh    16
#define Hh    128
#define ROWS  32
#define THREADS 512
#define CTAS  128
#define HEAD_IN 144
#define OUTD  60
#define SQ    (Hh*Hh)
#define NPAIR (Hh/2)

typedef unsigned long long ull;

#define FMA2(acc, a, b) \
    asm("fma.rn.f32x2 %0, %1, %2, %3;" : "=l"(acc) : "l"(a), "l"(b), "l"(acc))
#define PACK2(d, lo, hi) \
    asm("mov.b64 %0, {%1, %2};" : "=l"(d) : "f"(lo), "f"(hi))

__device__ __forceinline__ float2 unpack2(ull v) {
    float2 r;
    asm("mov.b64 {%0, %1}, %2;" : "=f"(r.x), "=f"(r.y) : "l"(v));
    return r;
}

// pre-packed weights: [l][pair][k][3] = {(wi,wo),(wc,ui),(uo,uc)} as f32x2 pairs
__device__ ulonglong2 g_wg[2][NPAIR][Hh][3];
__device__ ull        g_wd[2][NPAIR][Hh];

__global__ void pack_kernel(const float* __restrict__ Wx,
                            const float* __restrict__ Uh,
                            const float* __restrict__ Wd)
{
    int idx = blockIdx.x * blockDim.x + threadIdx.x;      // 2*64*128
    if (idx >= 2 * NPAIR * Hh) return;
    int k = idx & (Hh - 1);
    int p = (idx >> 7) & (NPAIR - 1);
    int l = idx >> 13;
    int j0 = 2 * p, j1 = j0 + 1;

    const float* wx = Wx + (size_t)l * 4 * SQ;
    const float* uh = Uh + (size_t)l * 4 * SQ;

    ull wi, wo, wc, ui, uo, uc, wd;
    PACK2(wi, wx[1*SQ + j0*Hh + k], wx[1*SQ + j1*Hh + k]);
    PACK2(wo, wx[2*SQ + j0*Hh + k], wx[2*SQ + j1*Hh + k]);
    PACK2(wc, wx[3*SQ + j0*Hh + k], wx[3*SQ + j1*Hh + k]);
    PACK2(ui, uh[1*SQ + j0*Hh + k], uh[1*SQ + j1*Hh + k]);
    PACK2(uo, uh[2*SQ + j0*Hh + k], uh[2*SQ + j1*Hh + k]);
    PACK2(uc, uh[3*SQ + j0*Hh + k], uh[3*SQ + j1*Hh + k]);
    const float* wdm = Wd + (size_t)l * SQ;
    PACK2(wd, wdm[j0*Hh + k], wdm[j1*Hh + k]);

    ulonglong2 v;
    v.x = wi; v.y = wo; g_wg[l][p][k][0] = v;
    v.x = wc; v.y = ui; g_wg[l][p][k][1] = v;
    v.x = uo; v.y = uc; g_wg[l][p][k][2] = v;
    g_wd[l][p][k] = wd;
}

struct SM {
    float h[2][ROWS][Hh];
    float c[2][ROWS][Hh];
    float xin[ROWS][Hh];
    float ht[ROWS][Hh];
    float sv[ROWS][Hh];
    float wp[Dh][Hh];
    float histb[ROWS][Dh];
    float msk[ROWS];
    float dec[ROWS];
    int   last[ROWS];
};

// fast transcendentals (EX2/RCP based, rel err ~1e-6; safe vs 1e-3 tolerance)
__device__ __forceinline__ float tanh_f(float x) {
    float e = __expf(2.0f * x);
    return 1.0f - __fdividef(2.0f, e + 1.0f);
}
__device__ __forceinline__ float sig_f(float x) {
    return __fdividef(1.0f, 1.0f + __expf(-x));
}

__device__ __forceinline__ float fixv(float x) {
    if (!(x == x)) return 0.0f;
    if (x > 1e38f) return 1e4f;
    if (x < -1e38f) return -1e4f;
    return x;
}

__global__ void __launch_bounds__(THREADS, 1)
tlstm_kernel(const float* __restrict__ history, const float* __restrict__ hmask,
             const float* __restrict__ Wp,  const float* __restrict__ bp,
             const float* __restrict__ bx,  const float* __restrict__ bd,
             const float* __restrict__ Wt,  const float* __restrict__ bt,
             const float* __restrict__ ln_g, const float* __restrict__ ln_b,
             const float* __restrict__ W1,  const float* __restrict__ b1,
             const float* __restrict__ W2,  const float* __restrict__ b2,
             float* __restrict__ out)
{
    extern __shared__ char smraw[];
    SM* sm = reinterpret_cast<SM*>(smraw);

    const int tid  = threadIdx.x;
    const int b0   = blockIdx.x * ROWS;
    const int w    = tid >> 5;
    const int lane = tid & 31;
    const int wk   = w & 7;
    const int wr   = w >> 3;
    const int half = lane >> 4;
    const int kk   = lane & 15;
    const int k    = wk * 16 + kk;
    const int rb   = wr * 16 + half * 8;

    for (int i = tid; i < 2 * ROWS * Hh; i += THREADS) {
        (&sm->h[0][0][0])[i] = 0.0f;
        (&sm->c[0][0][0])[i] = 0.0f;
    }
    for (int i = tid; i < Dh * Hh; i += THREADS)
        (&sm->wp[0][0])[i] = Wp[i];
    if (tid < ROWS) {
        const float* mp = hmask + (size_t)(b0 + tid) * Lh;
        float s = 0.0f;
        for (int t = 0; t < Lh; t++) s += mp[t];
        s = fminf(fmaxf(s, 1.0f), (float)Lh);
        sm->last[tid] = (int)s - 1;
    }
    __syncthreads();

    const float bpk  = bp[k];
    const float bxi0 = bx[1*Hh + k], bxo0 = bx[2*Hh + k], bxc0 = bx[3*Hh + k];
    const float bxi1 = bx[5*Hh + k], bxo1 = bx[6*Hh + k], bxc1 = bx[7*Hh + k];
    const float bd0  = bd[k],      bd1 = bd[Hh + k];
    const float wt0  = Wt[k],      wt1 = Wt[Hh + k];
    const float bt0  = bt[k],      bt1 = bt[Hh + k];

    // ================= time loop =================
    for (int t = 0; t < Lh; t++) {
        {
            int r = tid >> 4, d = tid & 15;
            sm->histb[r][d] = history[((size_t)(b0 + r) * Lh + t) * Dh + d];
            if (tid < ROWS)
                sm->msk[tid] = hmask[(size_t)(b0 + tid) * Lh + t];
        }
        __syncthreads();

        if (tid < ROWS) {
            float dd = fmaxf(sm->histb[tid][5], 0.0f);
            sm->dec[tid] = 1.0f / logf(2.718281828459045f + dd);
        }
        // x_t = hist @ Wp + bp
        {
            float acc[8];
            #pragma unroll
            for (int rr = 0; rr < 8; rr++) acc[rr] = bpk;
            #pragma unroll
            for (int d = 0; d < Dh; d++) {
                float wv = sm->wp[d][k];
                #pragma unroll
                for (int rr = 0; rr < 8; rr++)
                    acc[rr] += sm->histb[rb + rr][d] * wv;
            }
            #pragma unroll
            for (int rr = 0; rr < 8; rr++) sm->xin[rb + rr][k] = acc[rr];
        }
        __syncthreads();

        #pragma unroll
        for (int l = 0; l < 2; l++) {
            const float* inp  = (l == 0) ? &sm->xin[0][0] : &sm->h[0][0][0];
            float*       hcur = &sm->h[l][0][0];

            ull zi2[8], zo2[8], zc2[8];
            {
                const float bi = l ? bxi1 : bxi0;
                const float bo = l ? bxo1 : bxo0;
                const float bc = l ? bxc1 : bxc0;
                #pragma unroll
                for (int rr = 0; rr < 8; rr++) {
                    PACK2(zi2[rr], bi, 0.0f);
                    PACK2(zo2[rr], bo, 0.0f);
                    PACK2(zc2[rr], bc, 0.0f);
                }
            }

            // gate GEMV: pre-packed weights, 3x LDG.128 per j-pair
            const ulonglong2* __restrict__ pw = &g_wg[l][0][k][0];
            #pragma unroll 2
            for (int p = 0; p < NPAIR; p++) {
                ulonglong2 wa = pw[0];   // (wi, wo)
                ulonglong2 wb = pw[1];   // (wc, ui)
                ulonglong2 wd = pw[2];   // (uo, uc)
                const int j = 2 * p;
                #pragma unroll
                for (int rr = 0; rr < 8; rr++) {
                    const int r = rb + rr;
                    ull xu = *reinterpret_cast<const ull*>(inp  + r*Hh + j);
                    ull hu = *reinterpret_cast<const ull*>(hcur + r*Hh + j);
                    FMA2(zi2[rr], xu, wa.x);
                    FMA2(zo2[rr], xu, wa.y);
                    FMA2(zc2[rr], xu, wb.x);
                    FMA2(zi2[rr], hu, wb.y);
                    FMA2(zo2[rr], hu, wd.x);
                    FMA2(zc2[rr], hu, wd.y);
                }
                pw += Hh * 3;
            }

            float ot[8], htl[8];
            #pragma unroll
            for (int rr = 0; rr < 8; rr++) {
                float2 a = unpack2(zi2[rr]);
                float2 b = unpack2(zo2[rr]);
                float2 c = unpack2(zc2[rr]);
                float it = sig_f(a.x + a.y);
                ot[rr]   = sig_f(b.x + b.y);
                htl[rr]  = tanh_f(c.x + c.y) + it;
                sm->ht[rb + rr][k] = htl[rr];
            }
            __syncthreads();

            // h_short = tanh(h_tilde @ Wd + bd)
            const ull* __restrict__ pd = &g_wd[l][0][k];
            const float bdl = l ? bd1 : bd0;
            ull hs2[8];
            #pragma unroll
            for (int rr = 0; rr < 8; rr++) PACK2(hs2[rr], bdl, 0.0f);
            #pragma unroll 4
            for (int p = 0; p < NPAIR; p++) {
                ull wd2 = *pd;
                const int j = 2 * p;
                #pragma unroll
                for (int rr = 0; rr < 8; rr++) {
                    ull t2 = *reinterpret_cast<const ull*>(&sm->ht[rb + rr][j]);
                    FMA2(hs2[rr], t2, wd2);
                }
                pd += Hh;
            }

            const float wtl = l ? wt1 : wt0;
            const float btl = l ? bt1 : bt0;
            #pragma unroll
            for (int rr = 0; rr < 8; rr++) {
                const int r = rb + rr;
                float2 av   = unpack2(hs2[rr]);
                float hs    = tanh_f(av.x + av.y);
                float dt    = sig_f(sm->dec[r] * wtl + btl);
                float hstar = (htl[rr] - hs) + hs * dt;
                float cold  = sm->c[l][r][k];
                float cn    = tanh_f(hstar + ot[rr] * cold);
                float hn    = ot[rr] * tanh_f(cn);
                float m     = sm->msk[r];
                float hv    = m * hn + (1.0f - m) * hcur[r*Hh + k];
                float cv    = m * cn + (1.0f - m) * cold;
                sm->c[l][r][k] = cv;
                hcur[r*Hh + k] = hv;
                if (l == 1 && t == sm->last[r])
                    sm->sv[r][k] = m * hv;
            }
            __syncthreads();
        }
    }

    // ================= forecast head =================
    {
        int r = tid >> 4, d = tid & 15;
        sm->histb[r][d] = history[((size_t)(b0 + r) * Lh + sm->last[r]) * Dh + d];
    }
    __syncthreads();

    const unsigned FULL = 0xffffffffu;
    #pragma unroll
    for (int rr = 0; rr < 2; rr++) {
        const int r = w * 2 + rr;

        float s = 0.0f, s2 = 0.0f;
        for (int i = lane; i < HEAD_IN; i += 32) {
            float v = (i < 16) ? sm->histb[r][i] : sm->sv[r][i - 16];
            s += v; s2 += v * v;
        }
        #pragma unroll
        for (int off = 16; off; off >>= 1) {
            s  += __shfl_xor_sync(FULL, s,  off);
            s2 += __shfl_xor_sync(FULL, s2, off);
        }
        float mean = s / (float)HEAD_IN;
        float var  = s2 / (float)HEAD_IN - mean * mean;
        float rstd = rsqrtf(var + 1e-5f);

        const int j0 = lane * 4;
        float4 acc = *reinterpret_cast<const float4*>(b1 + j0);
        for (int i = 0; i < HEAD_IN; i++) {
            float v  = (i < 16) ? sm->histb[r][i] : sm->sv[r][i - 16];
            float sn = (v - mean) * rstd * ln_g[i] + ln_b[i];
            float4 w4 = *reinterpret_cast<const float4*>(W1 + i * Hh + j0);
            acc.x += sn * w4.x; acc.y += sn * w4.y;
            acc.z += sn * w4.z; acc.w += sn * w4.w;
        }
        float y[4] = { fmaxf(acc.x, 0.0f), fmaxf(acc.y, 0.0f),
                       fmaxf(acc.z, 0.0f), fmaxf(acc.w, 0.0f) };

        const int o0 = lane, o1 = lane + 32;
        float a0 = b2[o0];
        float a1 = (o1 < OUTD) ? b2[o1] : 0.0f;
        #pragma unroll
        for (int q = 0; q < 4; q++) {
            float yq = y[q];
            #pragma unroll 8
            for (int src = 0; src < 32; src++) {
                float v = __shfl_sync(FULL, yq, src);
                int   j = src * 4 + q;
                a0 += v * W2[j * OUTD + o0];
                if (o1 < OUTD) a1 += v * W2[j * OUTD + o1];
            }
        }
        size_t ob = (size_t)(b0 + r) * OUTD;
        out[ob + o0] = fixv(a0);
        if (o1 < OUTD) out[ob + o1] = fixv(a1);
    }
}

extern "C" void kernel_launch(void* const* d_in, const int* in_sizes, int n_in,
                              void* d_out, int out_size)
{
    const float* history = (const float*)d_in[0];
    const float* hmask   = (const float*)d_in[1];
    const float* Wp      = (const float*)d_in[2];
    const float* bp      = (const float*)d_in[3];
    const float* Wx      = (const float*)d_in[4];
    const float* bx      = (const float*)d_in[5];
    const float* Uh      = (const float*)d_in[6];
    const float* Wd      = (const float*)d_in[7];
    const float* bd      = (const float*)d_in[8];
    const float* Wt      = (const float*)d_in[9];
    const float* bt      = (const float*)d_in[10];
    const float* ln_g    = (const float*)d_in[11];
    const float* ln_b    = (const float*)d_in[12];
    const float* W1      = (const float*)d_in[13];
    const float* b1      = (const float*)d_in[14];
    const float* W2      = (const float*)d_in[15];
    const float* b2      = (const float*)d_in[16];

    pack_kernel<<<(2 * NPAIR * Hh + 255) / 256, 256>>>(Wx, Uh, Wd);

    cudaFuncSetAttribute(tlstm_kernel,
                         cudaFuncAttributeMaxDynamicSharedMemorySize,
                         (int)sizeof(SM));
    tlstm_kernel<<<CTAS, THREADS, sizeof(SM)>>>(
        history, hmask, Wp, bp, bx, bd, Wt, bt,
        ln_g, ln_b, W1, b1, W2, b2, (float*)d_out);
}